// round 11
// baseline (speedup 1.0000x reference)
#include <cuda_runtime.h>
#include <cuda_bf16.h>
#include <stdint.h>

// ============================================================================
// Problem constants
// ============================================================================
#define NROWS 8192
#define DIMK  256
#define NLBL  1024
#define NRT   64                       // 128-row tiles
#define NJOBS 2080                     // upper-triangular tiles: 64*65/2
#define MAXSEG 8
#define MAXCTA 256
#define TEMP_INV 14.285714285714286f   // 1/0.07
// exp((d-1)/T) = 2^(d*K - K), K = (1/T)*log2(e)
#define K_EX2 20.609929191666664f

// ============================================================================
// Device scratch (no allocation allowed)
// ============================================================================
__device__ __align__(128) __nv_bfloat16 g_en[NROWS * DIMK];  // normalized rows, bf16
__device__ int   g_lbl[NROWS];
__device__ int   g_hist[NLBL];
__device__ int   g_is64;
__device__ float g_diag[NROWS];                 // self-dot of bf16 row (fp32)
__device__ __align__(128) float g_C[NLBL * DIMK];  // class-sum vectors (fp32)
__device__ float g_colS[128][NRT][NRT];         // col exp-sums: [rit][ctile][rtile]
__device__ float g_S2[MAXCTA][MAXSEG][128];     // per-(CTA, segment) row exp-sum partials
__device__ int   g_seg_r[MAXCTA][MAXSEG];       // rtile id of each segment
__device__ float g_pb[256];                     // per-block partial losses
__device__ int   g_done;                        // finalize completion counter

// ============================================================================
// PTX helpers (baseline sm_80+ only — target is compute_103 WITHOUT 'a')
// ============================================================================
__device__ __forceinline__ uint32_t smem_u32(const void* p) {
    uint32_t a;
    asm("{ .reg .u64 t; cvta.to.shared.u64 t, %1; cvt.u32.u64 %0, t; }" : "=r"(a) : "l"(p));
    return a;
}

__device__ __forceinline__ void cp16(uint32_t dst, const void* src) {
    asm volatile("cp.async.cg.shared.global [%0], [%1], 16;" :: "r"(dst), "l"(src));
}
#define CP_COMMIT() asm volatile("cp.async.commit_group;" ::: "memory")
#define CP_WAIT0()  asm volatile("cp.async.wait_group 0;" ::: "memory")

__device__ __forceinline__ void ldsm4(uint32_t* r, uint32_t addr) {
    asm volatile("ldmatrix.sync.aligned.m8n8.x4.shared.b16 {%0,%1,%2,%3}, [%4];"
        : "=r"(r[0]), "=r"(r[1]), "=r"(r[2]), "=r"(r[3]) : "r"(addr));
}

__device__ __forceinline__ void mma16816(float* d, const uint32_t* a, const uint32_t* b) {
    asm volatile(
        "mma.sync.aligned.m16n8k16.row.col.f32.bf16.bf16.f32 "
        "{%0,%1,%2,%3}, {%4,%5,%6,%7}, {%8,%9}, {%0,%1,%2,%3};"
        : "+f"(d[0]), "+f"(d[1]), "+f"(d[2]), "+f"(d[3])
        : "r"(a[0]), "r"(a[1]), "r"(a[2]), "r"(a[3]), "r"(b[0]), "r"(b[1]));
}

__device__ __forceinline__ float ex2f(float x) {
    float e;
    asm("ex2.approx.f32 %0, %1;" : "=f"(e) : "f"(x));
    return e;
}

// ============================================================================
// SMEM layout (padded K-major tiles: 128 rows x 264 bf16 -> 528 B row stride)
// ============================================================================
#define ROWB   528
#define TILEB  (128 * ROWB)                 // 67584
#define SOFF_A   0
#define SOFF_B0  TILEB
#define SOFF_ROW (3 * TILEB)                // sS[4][128] (2 KB)
#define SOFF_COL (3 * TILEB + 2048)         // sCS[2][4][128] (4 KB)
#define SMEM_TOTAL (3 * TILEB + 2048 + 4096)  // 208896

// Fill one 128-row x 256-col bf16 tile via cp.async. 512 threads, 4096 chunks.
__device__ __forceinline__ void load_tile(uint32_t dst_base, int grow_base, int tid) {
    #pragma unroll
    for (int i = 0; i < 8; i++) {
        int c = tid + i * 512;     // 0..4095
        int r = c >> 5;            // row
        int q = c & 31;            // 16B chunk
        cp16(dst_base + r * ROWB + q * 16,
             (const void*)(g_en + (size_t)(grow_base + r) * DIMK + q * 8));
    }
}

// ============================================================================
// Kernel 1: block 0: zero hist/seg_r/counter + detect labels dtype;
// blocks 1..64: zero g_C
// ============================================================================
__global__ void init_kernel(const int* lab32) {
    int tid = threadIdx.x;  // 1024
    if (blockIdx.x == 0) {
        if (tid < NLBL) g_hist[tid] = 0;
        if (tid < MAXCTA * MAXSEG) ((int*)g_seg_r)[tid] = -1;
        if (tid + 1024 < MAXCTA * MAXSEG) ((int*)g_seg_r)[tid + 1024] = -1;
        if (tid == 0) g_done = 0;
        __shared__ int any;
        if (tid == 0) any = 0;
        __syncthreads();
        for (int i = tid; i < 4096; i += 1024)
            if (lab32[2 * i + 1] != 0) any = 1;  // benign race
        __syncthreads();
        if (tid == 0) g_is64 = (any == 0) ? 1 : 0;
    } else {
        ((float4*)g_C)[(blockIdx.x - 1) * 1024 + tid] = make_float4(0.f, 0.f, 0.f, 0.f);
    }
}

// ============================================================================
// Kernel 2: normalize rows -> bf16 (warp per row), labels, histogram,
// self-dot, class-sum accumulation (fp32 atomics, low contention)
// ============================================================================
__global__ void prep_kernel(const float* __restrict__ emb, const void* __restrict__ labels) {
    int warp = threadIdx.x >> 5, lane = threadIdx.x & 31;
    int row = blockIdx.x * 8 + warp;
    const float4* src = (const float4*)(emb + (size_t)row * DIMK);
    float4 v0 = __ldg(src + lane);
    float4 v1 = __ldg(src + lane + 32);
    float ss = v0.x * v0.x + v0.y * v0.y + v0.z * v0.z + v0.w * v0.w
             + v1.x * v1.x + v1.y * v1.y + v1.z * v1.z + v1.w * v1.w;
    #pragma unroll
    for (int o = 16; o; o >>= 1) ss += __shfl_xor_sync(0xffffffffu, ss, o);
    float inv = 1.0f / fmaxf(sqrtf(ss), 1e-12f);
    __nv_bfloat16 b[8];
    b[0] = __float2bfloat16(v0.x * inv); b[1] = __float2bfloat16(v0.y * inv);
    b[2] = __float2bfloat16(v0.z * inv); b[3] = __float2bfloat16(v0.w * inv);
    b[4] = __float2bfloat16(v1.x * inv); b[5] = __float2bfloat16(v1.y * inv);
    b[6] = __float2bfloat16(v1.z * inv); b[7] = __float2bfloat16(v1.w * inv);
    __nv_bfloat162* d2 = (__nv_bfloat162*)(g_en + (size_t)row * DIMK);
    d2[2 * lane + 0]  = __nv_bfloat162(b[0], b[1]);
    d2[2 * lane + 1]  = __nv_bfloat162(b[2], b[3]);
    d2[64 + 2 * lane] = __nv_bfloat162(b[4], b[5]);
    d2[65 + 2 * lane] = __nv_bfloat162(b[6], b[7]);
    float f[8], dd = 0.f;
    #pragma unroll
    for (int i = 0; i < 8; i++) {
        f[i] = __bfloat162float(b[i]);
        dd = fmaf(f[i], f[i], dd);
    }
    #pragma unroll
    for (int o = 16; o; o >>= 1) dd += __shfl_xor_sync(0xffffffffu, dd, o);
    int l;
    if (lane == 0) {
        g_diag[row] = dd;
        l = g_is64 ? (int)((const long long*)labels)[row] : ((const int*)labels)[row];
        g_lbl[row] = l;
        atomicAdd(&g_hist[l], 1);
    }
    l = __shfl_sync(0xffffffffu, l, 0);
    float* Cr = g_C + (size_t)l * DIMK;
    #pragma unroll
    for (int i = 0; i < 4; i++) atomicAdd(&Cr[4 * lane + i], f[i]);
    #pragma unroll
    for (int i = 0; i < 4; i++) atomicAdd(&Cr[128 + 4 * lane + i], f[4 + i]);
}

// ============================================================================
// Kernel 3: persistent symmetric fused GEMM (pair-folded triangular jobs).
// 512 threads = 16 warps (4M x 4N, 32x32 warp tiles). One exp feeds both
// row exp-sums (block r) and column exp-sums (block c). NO label work here.
// ============================================================================
typedef float Acc[2][4][4];  // [mf][j][r]

// reduce column partials across the 8 row-positions (lanes xor 4,8,16) + store
__device__ __forceinline__ void col_flush(
    char* smem, float* cS, int par, int warpM, int warpN, int lid)
{
    float* sCS = (float*)(smem + SOFF_COL) + par * 512;
    #pragma unroll
    for (int cj = 0; cj < 8; cj++) {
        float s = cS[cj];
        s += __shfl_xor_sync(0xffffffffu, s, 4);
        s += __shfl_xor_sync(0xffffffffu, s, 8);
        s += __shfl_xor_sync(0xffffffffu, s, 16);
        if (lid < 4) {
            int col = warpN * 32 + (cj >> 1) * 8 + 2 * lid + (cj & 1);
            sCS[warpM * 128 + col] = s;
        }
        cS[cj] = 0.f;
    }
}

template <bool HAS_PREV>
__device__ __forceinline__ void do_tile(
    int jc, int c_cur, int r, int segEnd, char* smem, uint32_t sb,
    int tid, int lid, int warpM, int warpN,
    uint32_t aAddr, uint32_t bOff,
    Acc& cur, Acc& prev, float* Sa, float* cS,
    int& pend_c, bool prev_offd)
{
    CP_WAIT0();
    __syncthreads();

    // prefetch next B tile within this segment
    if (jc + 1 < segEnd) {
        load_tile(sb + SOFF_B0 + ((jc + 1) & 1) * TILEB, (c_cur + 1) << 7, tid);
        CP_COMMIT();
    }
    // store previously-flushed column sums (parity of tile jc-2, safe post-sync)
    if (HAS_PREV && pend_c >= 0 && tid < 128) {
        float* sCS = (float*)(smem + SOFF_COL) + (jc & 1) * 512;  // (jc-2)&1 == jc&1
        g_colS[tid][pend_c][r] = sCS[tid] + sCS[128 + tid] + sCS[256 + tid] + sCS[384 + tid];
    }

    #pragma unroll
    for (int mf = 0; mf < 2; mf++)
        #pragma unroll
        for (int j = 0; j < 4; j++)
            #pragma unroll
            for (int rr = 0; rr < 4; rr++) cur[mf][j][rr] = 0.f;

    uint32_t bAddr = sb + SOFF_B0 + (jc & 1) * TILEB + bOff;

    #pragma unroll
    for (int ks = 0; ks < 16; ks++) {
        uint32_t a[2][4], b[2][4];
        ldsm4(a[0], aAddr + ks * 32);
        ldsm4(a[1], aAddr + 16 * ROWB + ks * 32);
        ldsm4(b[0], bAddr + ks * 32);
        ldsm4(b[1], bAddr + 16 * ROWB + ks * 32);
        #pragma unroll
        for (int mf = 0; mf < 2; mf++)
            #pragma unroll
            for (int jj = 0; jj < 2; jj++) {
                mma16816(cur[mf][2 * jj + 0], a[mf], &b[jj][0]);
                mma16816(cur[mf][2 * jj + 1], a[mf], &b[jj][2]);
            }
        if (HAS_PREV) {
            // interleaved epilogue: 2 values of previous tile's acc per ks step
            #pragma unroll
            for (int u = 0; u < 2; u++) {
                const int v = 2 * ks + u;
                const int mf = v >> 4, j = (v >> 2) & 3, rr = v & 3;
                const int hi = rr >> 1, lo = rr & 1;
                float e = ex2f(fmaf(prev[mf][j][rr], K_EX2, -K_EX2));
                Sa[mf * 2 + hi] += e;
                cS[j * 2 + lo] += e;
            }
        }
    }

    if (HAS_PREV) {
        if (prev_offd) {
            col_flush(smem, cS, (jc - 1) & 1, warpM, warpN, lid);
            pend_c = c_cur - 1;
        } else {
            // previous tile was the diagonal: its column sums are already
            // counted as rows — discard
            #pragma unroll
            for (int i = 0; i < 8; i++) cS[i] = 0.f;
            pend_c = -1;
        }
    }
}

__device__ __forceinline__ void drain_acc(Acc& acc, float* Sa, float* cS) {
    #pragma unroll
    for (int v = 0; v < 32; v++) {
        const int mf = v >> 4, j = (v >> 2) & 3, rr = v & 3;
        const int hi = rr >> 1, lo = rr & 1;
        float e = ex2f(fmaf(acc[mf][j][rr], K_EX2, -K_EX2));
        Sa[mf * 2 + hi] += e;
        cS[j * 2 + lo] += e;
    }
}

__global__ void __launch_bounds__(512, 1) gemm_kernel(int ncta) {
    extern __shared__ char smem[];
    uint32_t sb = smem_u32(smem);
    float (*sS)[128] = (float(*)[128])(smem + SOFF_ROW);
    int tid = threadIdx.x, wid = tid >> 5, lid = tid & 31;
    int warpM = wid & 3, warpN = wid >> 2;  // 4 x 4 warp grid, 32x32 warp tiles
    int bid = blockIdx.x;
    int start = (bid * NJOBS) / ncta;
    int end = ((bid + 1) * NJOBS) / ncta;

    // row-in-tile covered by each of this lane's 4 acc row-groups
    int rit[4];
    #pragma unroll
    for (int idx = 0; idx < 4; idx++)
        rit[idx] = warpM * 32 + (idx >> 1) * 16 + (idx & 1) * 8 + (lid >> 2);

    // ldmatrix per-lane base addresses
    uint32_t aAddr = sb + SOFF_A
        + (uint32_t)(warpM * 32 + (lid & 7) + ((lid >> 3) & 1) * 8) * ROWB
        + ((lid >> 4) & 1) * 16;
    uint32_t bOff =
        (uint32_t)(warpN * 32 + (lid & 7) + ((lid >> 4) & 1) * 8) * ROWB
        + ((lid >> 3) & 1) * 16;

    Acc acc0, acc1;
    float Sa[4], cS[8];
    #pragma unroll
    for (int i = 0; i < 8; i++) cS[i] = 0.f;

    int job = start, seg = 0, pend_c = -1;

    while (job < end) {
        // decode pair-folded run containing job:
        // pair p = row p (head, 64-p jobs) then row 63-p (tail, p+1 jobs)
        int p = job / 65, q = job - 65 * p, h = 64 - p;
        int r, run_start, run_end;
        if (q < h) { r = p;      run_start = 65 * p;     run_end = run_start + h; }
        else       { r = 63 - p; run_start = 65 * p + h; run_end = 65 * (p + 1);  }
        int segEnd = min(end, run_end);
        int row_base = r << 7;
        int c0 = r + (job - run_start);
        #pragma unroll
        for (int idx = 0; idx < 4; idx++) Sa[idx] = 0.f;

        // segment prologue: A tile + first B tile as one cp.async group
        load_tile(sb + SOFF_A, row_base, tid);
        load_tile(sb + SOFF_B0 + (job & 1) * TILEB, c0 << 7, tid);
        CP_COMMIT();

        int n = segEnd - job;
        do_tile<false>(job, c0, r, segEnd, smem, sb, tid, lid, warpM, warpN,
                       aAddr, bOff, acc0, acc1, Sa, cS, pend_c, false);
        int k = 1;
        while (k + 2 <= n) {
            do_tile<true>(job + k, c0 + k, r, segEnd, smem, sb, tid, lid, warpM, warpN,
                          aAddr, bOff, acc1, acc0, Sa, cS, pend_c, (c0 + k - 1) != r);
            do_tile<true>(job + k + 1, c0 + k + 1, r, segEnd, smem, sb, tid, lid, warpM, warpN,
                          aAddr, bOff, acc0, acc1, Sa, cS, pend_c, true);
            k += 2;
        }
        int cL = c0 + n - 1;            // column of last tile
        bool offd_last = (cL != r);
        if (k < n) {
            do_tile<true>(job + k, c0 + k, r, segEnd, smem, sb, tid, lid, warpM, warpN,
                          aAddr, bOff, acc1, acc0, Sa, cS, pend_c, (c0 + k - 1) != r);
            drain_acc(acc1, Sa, cS);
        } else {
            drain_acc(acc0, Sa, cS);
        }

        // flush last tile's columns (or discard if it was the diagonal)
        int parL = (segEnd - 1) & 1;
        if (offd_last) {
            col_flush(smem, cS, parL, warpM, warpN, lid);
        } else {
            #pragma unroll
            for (int i = 0; i < 8; i++) cS[i] = 0.f;
        }

        // row partials: quad reduce -> smem
        #pragma unroll
        for (int idx = 0; idx < 4; idx++) {
            float s = Sa[idx];
            s += __shfl_xor_sync(0xffffffffu, s, 1);
            s += __shfl_xor_sync(0xffffffffu, s, 2);
            if ((lid & 3) == 0) sS[warpN][rit[idx]] = s;
        }
        __syncthreads();
        if (tid < 128) {
            if (pend_c >= 0) {   // second-to-last tile's columns
                float* sCS = (float*)(smem + SOFF_COL) + ((segEnd - 2) & 1) * 512;
                g_colS[tid][pend_c][r] = sCS[tid] + sCS[128 + tid] + sCS[256 + tid] + sCS[384 + tid];
            }
            if (offd_last) {     // last tile's columns
                float* sCS = (float*)(smem + SOFF_COL) + parL * 512;
                g_colS[tid][cL][r] = sCS[tid] + sCS[128 + tid] + sCS[256 + tid] + sCS[384 + tid];
            }
            g_S2[bid][seg][tid] = sS[0][tid] + sS[1][tid] + sS[2][tid] + sS[3][tid];
        }
        if (tid == 0) g_seg_r[bid][seg] = r;
        __syncthreads();  // protects smem buffers before next segment
        pend_c = -1;
        job = segEnd;
        seg++;
    }
}

// ============================================================================
// Kernel 4: per-row loss, warp per row. 256 blocks x 1024 threads.
// S: coalesced column gather + lane-parallel segment scan.
// P: 256-dim dot with the class-sum vector.
// Last block combines all block partials (deterministic, fixed order).
// ============================================================================
__global__ void finalize_kernel(float* __restrict__ out, int ncta) {
    int tid = threadIdx.x, warp = tid >> 5, lane = tid & 31;
    int row = blockIdx.x * 32 + warp;
    int b = row >> 7, rit = row & 127;
    int lbl = __ldg(&g_lbl[row]);

    // ---- P = <e_row, C[lbl]> - diag ----
    const __nv_bfloat162* er = (const __nv_bfloat162*)(g_en + (size_t)row * DIMK);
    const float2* Cr = (const float2*)(g_C + (size_t)lbl * DIMK);
    float P = 0.f;
    #pragma unroll
    for (int i = 0; i < 4; i++) {
        int idx = lane + 32 * i;
        __nv_bfloat162 v = er[idx];
        float2 c = __ldg(&Cr[idx]);
        P = fmaf(__bfloat162float(v.x), c.x, P);
        P = fmaf(__bfloat162float(v.y), c.y, P);
    }

    // ---- S: columns of tiles (r2, b), r2 < b (coalesced over lanes) ----
    float S = 0.f;
    for (int r2 = lane; r2 < b; r2 += 32)
        S += g_colS[rit][b][r2];

    // ---- S: row segments with r == b ----
    int u0, u1;
    if (b < 32) { u0 = 65 * b; u1 = u0 + (64 - b) - 1; }
    else { int p = 63 - b; u0 = 65 * p + (64 - p); u1 = 65 * (p + 1) - 1; }
    int jlo = (int)(((long long)u0 * ncta) / NJOBS) - 2; if (jlo < 0) jlo = 0;
    int jhi = (int)(((long long)u1 * ncta) / NJOBS) + 2; if (jhi > ncta - 1) jhi = ncta - 1;
    int npairs = (jhi - jlo + 1) * MAXSEG;
    for (int i = lane; i < npairs; i += 32) {
        int qq = jlo + i / MAXSEG, sg = i - (i / MAXSEG) * MAXSEG;
        if (g_seg_r[qq][sg] == b) S += g_S2[qq][sg][rit];
    }

    #pragma unroll
    for (int o = 16; o; o >>= 1) {
        S += __shfl_xor_sync(0xffffffffu, S, o);
        P += __shfl_xor_sync(0xffffffffu, P, o);
    }
    float acc = 0.f;
    if (lane == 0) {
        P -= g_diag[row];  // exclude self from positives
        int cnt = g_hist[lbl] - 1;
        acc = (cnt > 0) ? (TEMP_INV + __logf(S) - (P * TEMP_INV) / (float)cnt) : 0.f;
    }
    __shared__ float ws[32];
    if (lane == 0) ws[warp] = acc;
    __syncthreads();
    if (tid < 32) {
        float v = ws[tid];
        #pragma unroll
        for (int o = 16; o; o >>= 1) v += __shfl_xor_sync(0xffffffffu, v, o);
        if (tid == 0) {
            g_pb[blockIdx.x] = v;
            __threadfence();
            int prev = atomicAdd(&g_done, 1);
            if (prev == 255) {  // last block: fixed-order combine (deterministic)
                float tot = 0.f;
                #pragma unroll 8
                for (int bb = 0; bb < 256; bb++) tot += ((volatile float*)g_pb)[bb];
                out[0] = tot / (float)NROWS;
            }
        }
    }
}

// ============================================================================
// Launch
// ============================================================================
extern "C" void kernel_launch(void* const* d_in, const int* in_sizes, int n_in,
                              void* d_out, int out_size) {
    const float* emb;
    const void* lab;
    if (in_sizes[0] == NROWS * DIMK) {
        emb = (const float*)d_in[0];
        lab = d_in[1];
    } else {
        emb = (const float*)d_in[1];
        lab = d_in[0];
    }

    int dev = 0;
    cudaGetDevice(&dev);
    int ncta = 0;
    cudaDeviceGetAttribute(&ncta, cudaDevAttrMultiProcessorCount, dev);
    if (ncta < 100 || ncta > MAXCTA) ncta = 128;

    cudaFuncSetAttribute(gemm_kernel, cudaFuncAttributeMaxDynamicSharedMemorySize, SMEM_TOTAL);

    init_kernel<<<65, 1024>>>((const int*)lab);
    prep_kernel<<<NROWS / 8, 256>>>(emb, lab);
    gemm_kernel<<<ncta, 512, SMEM_TOTAL>>>(ncta);
    finalize_kernel<<<256, 1024>>>((float*)d_out, ncta);
}

// round 12
// speedup vs baseline: 1.0787x; 1.0787x over previous
#include <cuda_runtime.h>
#include <cuda_bf16.h>
#include <stdint.h>

// ============================================================================
// Problem constants
// ============================================================================
#define NROWS 8192
#define DIMK  256
#define NLBL  1024
#define NRT   64                       // 128-row tiles
#define NJOBS 2080                     // upper-triangular tiles: 64*65/2
#define MAXSEG 8
#define MAXCTA 256
#define TEMP_INV 14.285714285714286f   // 1/0.07
// exp((d-1)/T) = 2^(d*K - K), K = (1/T)*log2(e)
#define K_EX2 20.609929191666664f

// ============================================================================
// Device scratch (no allocation allowed)
// ============================================================================
__device__ __align__(128) __nv_bfloat16 g_en[NROWS * DIMK];  // normalized rows, bf16
__device__ int   g_lbl[NROWS];
__device__ int   g_hist[NLBL];
__device__ int   g_is64;
__device__ float g_diag[NROWS];                 // self-dot of bf16 row (fp32)
__device__ __align__(128) float g_C[NLBL * DIMK];  // class-sum vectors (fp32)
__device__ float g_colS[128][NRT][NRT];         // col exp-sums: [rit][ctile][rtile]
__device__ float g_S2[MAXCTA][MAXSEG][128];     // per-(CTA, segment) row exp-sum partials
__device__ int   g_seg_r[MAXCTA][MAXSEG];       // rtile id of each segment
__device__ float g_pb[256];                     // per-block partial losses

// ============================================================================
// PTX helpers (baseline sm_80+ only — target is compute_103 WITHOUT 'a')
// ============================================================================
__device__ __forceinline__ uint32_t smem_u32(const void* p) {
    uint32_t a;
    asm("{ .reg .u64 t; cvta.to.shared.u64 t, %1; cvt.u32.u64 %0, t; }" : "=r"(a) : "l"(p));
    return a;
}

__device__ __forceinline__ void cp16(uint32_t dst, const void* src) {
    asm volatile("cp.async.cg.shared.global [%0], [%1], 16;" :: "r"(dst), "l"(src));
}
#define CP_COMMIT() asm volatile("cp.async.commit_group;" ::: "memory")
#define CP_WAIT0()  asm volatile("cp.async.wait_group 0;" ::: "memory")

__device__ __forceinline__ void ldsm4(uint32_t* r, uint32_t addr) {
    asm volatile("ldmatrix.sync.aligned.m8n8.x4.shared.b16 {%0,%1,%2,%3}, [%4];"
        : "=r"(r[0]), "=r"(r[1]), "=r"(r[2]), "=r"(r[3]) : "r"(addr));
}

__device__ __forceinline__ void mma16816(float* d, const uint32_t* a, const uint32_t* b) {
    asm volatile(
        "mma.sync.aligned.m16n8k16.row.col.f32.bf16.bf16.f32 "
        "{%0,%1,%2,%3}, {%4,%5,%6,%7}, {%8,%9}, {%0,%1,%2,%3};"
        : "+f"(d[0]), "+f"(d[1]), "+f"(d[2]), "+f"(d[3])
        : "r"(a[0]), "r"(a[1]), "r"(a[2]), "r"(a[3]), "r"(b[0]), "r"(b[1]));
}

__device__ __forceinline__ float ex2f(float x) {
    float e;
    asm("ex2.approx.f32 %0, %1;" : "=f"(e) : "f"(x));
    return e;
}

// ============================================================================
// SMEM layout (padded K-major tiles: 128 rows x 264 bf16 -> 528 B row stride)
// ============================================================================
#define ROWB   528
#define TILEB  (128 * ROWB)                 // 67584
#define SOFF_A   0
#define SOFF_B0  TILEB
#define SOFF_ROW (3 * TILEB)                // sS[4][128] (2 KB)
#define SOFF_COL (3 * TILEB + 2048)         // sCS[2][4][128] (4 KB)
#define SMEM_TOTAL (3 * TILEB + 2048 + 4096)  // 208896

// Fill one 128-row x 256-col bf16 tile via cp.async. 512 threads, 4096 chunks.
__device__ __forceinline__ void load_tile(uint32_t dst_base, int grow_base, int tid) {
    #pragma unroll
    for (int i = 0; i < 8; i++) {
        int c = tid + i * 512;     // 0..4095
        int r = c >> 5;            // row
        int q = c & 31;            // 16B chunk
        cp16(dst_base + r * ROWB + q * 16,
             (const void*)(g_en + (size_t)(grow_base + r) * DIMK + q * 8));
    }
}

// ============================================================================
// Kernel 1: block 0: zero hist/seg_r + detect labels dtype; blocks 1..64: zero g_C
// ============================================================================
__global__ void init_kernel(const int* lab32) {
    int tid = threadIdx.x;  // 1024
    if (blockIdx.x == 0) {
        if (tid < NLBL) g_hist[tid] = 0;
        if (tid < MAXCTA * MAXSEG) ((int*)g_seg_r)[tid] = -1;
        if (tid + 1024 < MAXCTA * MAXSEG) ((int*)g_seg_r)[tid + 1024] = -1;
        __shared__ int any;
        if (tid == 0) any = 0;
        __syncthreads();
        for (int i = tid; i < 4096; i += 1024)
            if (lab32[2 * i + 1] != 0) any = 1;  // benign race
        __syncthreads();
        if (tid == 0) g_is64 = (any == 0) ? 1 : 0;
    } else {
        ((float4*)g_C)[(blockIdx.x - 1) * 1024 + tid] = make_float4(0.f, 0.f, 0.f, 0.f);
    }
}

// ============================================================================
// Kernel 2: normalize rows -> bf16 (warp per row), labels, histogram,
// self-dot, class-sum accumulation (fp32 atomics, low contention)
// 1024 threads = 32 rows per block, 256 blocks.
// ============================================================================
__global__ void prep_kernel(const float* __restrict__ emb, const void* __restrict__ labels) {
    int warp = threadIdx.x >> 5, lane = threadIdx.x & 31;
    int row = blockIdx.x * 32 + warp;
    const float4* src = (const float4*)(emb + (size_t)row * DIMK);
    float4 v0 = __ldg(src + lane);
    float4 v1 = __ldg(src + lane + 32);
    float ss = v0.x * v0.x + v0.y * v0.y + v0.z * v0.z + v0.w * v0.w
             + v1.x * v1.x + v1.y * v1.y + v1.z * v1.z + v1.w * v1.w;
    #pragma unroll
    for (int o = 16; o; o >>= 1) ss += __shfl_xor_sync(0xffffffffu, ss, o);
    float inv = 1.0f / fmaxf(sqrtf(ss), 1e-12f);
    __nv_bfloat16 b[8];
    b[0] = __float2bfloat16(v0.x * inv); b[1] = __float2bfloat16(v0.y * inv);
    b[2] = __float2bfloat16(v0.z * inv); b[3] = __float2bfloat16(v0.w * inv);
    b[4] = __float2bfloat16(v1.x * inv); b[5] = __float2bfloat16(v1.y * inv);
    b[6] = __float2bfloat16(v1.z * inv); b[7] = __float2bfloat16(v1.w * inv);
    __nv_bfloat162* d2 = (__nv_bfloat162*)(g_en + (size_t)row * DIMK);
    d2[2 * lane + 0]  = __nv_bfloat162(b[0], b[1]);
    d2[2 * lane + 1]  = __nv_bfloat162(b[2], b[3]);
    d2[64 + 2 * lane] = __nv_bfloat162(b[4], b[5]);
    d2[65 + 2 * lane] = __nv_bfloat162(b[6], b[7]);
    float f[8], dd = 0.f;
    #pragma unroll
    for (int i = 0; i < 8; i++) {
        f[i] = __bfloat162float(b[i]);
        dd = fmaf(f[i], f[i], dd);
    }
    #pragma unroll
    for (int o = 16; o; o >>= 1) dd += __shfl_xor_sync(0xffffffffu, dd, o);
    int l;
    if (lane == 0) {
        g_diag[row] = dd;
        l = g_is64 ? (int)((const long long*)labels)[row] : ((const int*)labels)[row];
        g_lbl[row] = l;
        atomicAdd(&g_hist[l], 1);
    }
    l = __shfl_sync(0xffffffffu, l, 0);
    float* Cr = g_C + (size_t)l * DIMK;
    #pragma unroll
    for (int i = 0; i < 4; i++) atomicAdd(&Cr[4 * lane + i], f[i]);
    #pragma unroll
    for (int i = 0; i < 4; i++) atomicAdd(&Cr[128 + 4 * lane + i], f[4 + i]);
}

// ============================================================================
// Kernel 3: persistent symmetric fused GEMM (pair-folded triangular jobs).
// 512 threads = 16 warps (4M x 4N, 32x32 warp tiles). One exp feeds both
// row exp-sums (block r) and column exp-sums (block c). NO label work here.
// ============================================================================
typedef float Acc[2][4][4];  // [mf][j][r]

// reduce column partials across the 8 row-positions (lanes xor 4,8,16) + store
__device__ __forceinline__ void col_flush(
    char* smem, float* cS, int par, int warpM, int warpN, int lid)
{
    float* sCS = (float*)(smem + SOFF_COL) + par * 512;
    #pragma unroll
    for (int cj = 0; cj < 8; cj++) {
        float s = cS[cj];
        s += __shfl_xor_sync(0xffffffffu, s, 4);
        s += __shfl_xor_sync(0xffffffffu, s, 8);
        s += __shfl_xor_sync(0xffffffffu, s, 16);
        if (lid < 4) {
            int col = warpN * 32 + (cj >> 1) * 8 + 2 * lid + (cj & 1);
            sCS[warpM * 128 + col] = s;
        }
        cS[cj] = 0.f;
    }
}

template <bool HAS_PREV>
__device__ __forceinline__ void do_tile(
    int jc, int c_cur, int r, int segEnd, char* smem, uint32_t sb,
    int tid, int lid, int warpM, int warpN,
    uint32_t aAddr, uint32_t bOff,
    Acc& cur, Acc& prev, float* Sa, float* cS,
    int& pend_c, bool prev_offd)
{
    CP_WAIT0();
    __syncthreads();

    // prefetch next B tile within this segment
    if (jc + 1 < segEnd) {
        load_tile(sb + SOFF_B0 + ((jc + 1) & 1) * TILEB, (c_cur + 1) << 7, tid);
        CP_COMMIT();
    }
    // store previously-flushed column sums (parity of tile jc-2, safe post-sync)
    if (HAS_PREV && pend_c >= 0 && tid < 128) {
        float* sCS = (float*)(smem + SOFF_COL) + (jc & 1) * 512;  // (jc-2)&1 == jc&1
        g_colS[tid][pend_c][r] = sCS[tid] + sCS[128 + tid] + sCS[256 + tid] + sCS[384 + tid];
    }

    #pragma unroll
    for (int mf = 0; mf < 2; mf++)
        #pragma unroll
        for (int j = 0; j < 4; j++)
            #pragma unroll
            for (int rr = 0; rr < 4; rr++) cur[mf][j][rr] = 0.f;

    uint32_t bAddr = sb + SOFF_B0 + (jc & 1) * TILEB + bOff;

    #pragma unroll
    for (int ks = 0; ks < 16; ks++) {
        uint32_t a[2][4], b[2][4];
        ldsm4(a[0], aAddr + ks * 32);
        ldsm4(a[1], aAddr + 16 * ROWB + ks * 32);
        ldsm4(b[0], bAddr + ks * 32);
        ldsm4(b[1], bAddr + 16 * ROWB + ks * 32);
        #pragma unroll
        for (int mf = 0; mf < 2; mf++)
            #pragma unroll
            for (int jj = 0; jj < 2; jj++) {
                mma16816(cur[mf][2 * jj + 0], a[mf], &b[jj][0]);
                mma16816(cur[mf][2 * jj + 1], a[mf], &b[jj][2]);
            }
        if (HAS_PREV) {
            // interleaved epilogue: 2 values of previous tile's acc per ks step
            #pragma unroll
            for (int u = 0; u < 2; u++) {
                const int v = 2 * ks + u;
                const int mf = v >> 4, j = (v >> 2) & 3, rr = v & 3;
                const int hi = rr >> 1, lo = rr & 1;
                float e = ex2f(fmaf(prev[mf][j][rr], K_EX2, -K_EX2));
                Sa[mf * 2 + hi] += e;
                cS[j * 2 + lo] += e;
            }
        }
    }

    if (HAS_PREV) {
        if (prev_offd) {
            col_flush(smem, cS, (jc - 1) & 1, warpM, warpN, lid);
            pend_c = c_cur - 1;
        } else {
            // previous tile was the diagonal: its column sums are already
            // counted as rows — discard
            #pragma unroll
            for (int i = 0; i < 8; i++) cS[i] = 0.f;
            pend_c = -1;
        }
    }
}

__device__ __forceinline__ void drain_acc(Acc& acc, float* Sa, float* cS) {
    #pragma unroll
    for (int v = 0; v < 32; v++) {
        const int mf = v >> 4, j = (v >> 2) & 3, rr = v & 3;
        const int hi = rr >> 1, lo = rr & 1;
        float e = ex2f(fmaf(acc[mf][j][rr], K_EX2, -K_EX2));
        Sa[mf * 2 + hi] += e;
        cS[j * 2 + lo] += e;
    }
}

__global__ void __launch_bounds__(512, 1) gemm_kernel(int ncta) {
    extern __shared__ char smem[];
    uint32_t sb = smem_u32(smem);
    float (*sS)[128] = (float(*)[128])(smem + SOFF_ROW);
    int tid = threadIdx.x, wid = tid >> 5, lid = tid & 31;
    int warpM = wid & 3, warpN = wid >> 2;  // 4 x 4 warp grid, 32x32 warp tiles
    int bid = blockIdx.x;
    int start = (bid * NJOBS) / ncta;
    int end = ((bid + 1) * NJOBS) / ncta;

    // row-in-tile covered by each of this lane's 4 acc row-groups
    int rit[4];
    #pragma unroll
    for (int idx = 0; idx < 4; idx++)
        rit[idx] = warpM * 32 + (idx >> 1) * 16 + (idx & 1) * 8 + (lid >> 2);

    // ldmatrix per-lane base addresses
    uint32_t aAddr = sb + SOFF_A
        + (uint32_t)(warpM * 32 + (lid & 7) + ((lid >> 3) & 1) * 8) * ROWB
        + ((lid >> 4) & 1) * 16;
    uint32_t bOff =
        (uint32_t)(warpN * 32 + (lid & 7) + ((lid >> 4) & 1) * 8) * ROWB
        + ((lid >> 3) & 1) * 16;

    Acc acc0, acc1;
    float Sa[4], cS[8];
    #pragma unroll
    for (int i = 0; i < 8; i++) cS[i] = 0.f;

    int job = start, seg = 0, pend_c = -1;

    while (job < end) {
        // decode pair-folded run containing job:
        // pair p = row p (head, 64-p jobs) then row 63-p (tail, p+1 jobs)
        int p = job / 65, q = job - 65 * p, h = 64 - p;
        int r, run_start, run_end;
        if (q < h) { r = p;      run_start = 65 * p;     run_end = run_start + h; }
        else       { r = 63 - p; run_start = 65 * p + h; run_end = 65 * (p + 1);  }
        int segEnd = min(end, run_end);
        int row_base = r << 7;
        int c0 = r + (job - run_start);
        #pragma unroll
        for (int idx = 0; idx < 4; idx++) Sa[idx] = 0.f;

        // segment prologue: A tile + first B tile as one cp.async group
        load_tile(sb + SOFF_A, row_base, tid);
        load_tile(sb + SOFF_B0 + (job & 1) * TILEB, c0 << 7, tid);
        CP_COMMIT();

        int n = segEnd - job;
        do_tile<false>(job, c0, r, segEnd, smem, sb, tid, lid, warpM, warpN,
                       aAddr, bOff, acc0, acc1, Sa, cS, pend_c, false);
        int k = 1;
        while (k + 2 <= n) {
            do_tile<true>(job + k, c0 + k, r, segEnd, smem, sb, tid, lid, warpM, warpN,
                          aAddr, bOff, acc1, acc0, Sa, cS, pend_c, (c0 + k - 1) != r);
            do_tile<true>(job + k + 1, c0 + k + 1, r, segEnd, smem, sb, tid, lid, warpM, warpN,
                          aAddr, bOff, acc0, acc1, Sa, cS, pend_c, true);
            k += 2;
        }
        int cL = c0 + n - 1;            // column of last tile
        bool offd_last = (cL != r);
        if (k < n) {
            do_tile<true>(job + k, c0 + k, r, segEnd, smem, sb, tid, lid, warpM, warpN,
                          aAddr, bOff, acc1, acc0, Sa, cS, pend_c, (c0 + k - 1) != r);
            drain_acc(acc1, Sa, cS);
        } else {
            drain_acc(acc0, Sa, cS);
        }

        // flush last tile's columns (or discard if it was the diagonal)
        int parL = (segEnd - 1) & 1;
        if (offd_last) {
            col_flush(smem, cS, parL, warpM, warpN, lid);
        } else {
            #pragma unroll
            for (int i = 0; i < 8; i++) cS[i] = 0.f;
        }

        // row partials: quad reduce -> smem
        #pragma unroll
        for (int idx = 0; idx < 4; idx++) {
            float s = Sa[idx];
            s += __shfl_xor_sync(0xffffffffu, s, 1);
            s += __shfl_xor_sync(0xffffffffu, s, 2);
            if ((lid & 3) == 0) sS[warpN][rit[idx]] = s;
        }
        __syncthreads();
        if (tid < 128) {
            if (pend_c >= 0) {   // second-to-last tile's columns
                float* sCS = (float*)(smem + SOFF_COL) + ((segEnd - 2) & 1) * 512;
                g_colS[tid][pend_c][r] = sCS[tid] + sCS[128 + tid] + sCS[256 + tid] + sCS[384 + tid];
            }
            if (offd_last) {     // last tile's columns
                float* sCS = (float*)(smem + SOFF_COL) + parL * 512;
                g_colS[tid][cL][r] = sCS[tid] + sCS[128 + tid] + sCS[256 + tid] + sCS[384 + tid];
            }
            g_S2[bid][seg][tid] = sS[0][tid] + sS[1][tid] + sS[2][tid] + sS[3][tid];
        }
        if (tid == 0) g_seg_r[bid][seg] = r;
        __syncthreads();  // protects smem buffers before next segment
        pend_c = -1;
        job = segEnd;
        seg++;
    }
}

// ============================================================================
// Kernel 4: per-row loss, warp per row. 256 blocks x 1024 threads.
// S: coalesced column gather + lane-parallel segment scan.
// P: 256-dim dot with the class-sum vector.
// ============================================================================
__global__ void finalize_kernel(int ncta) {
    int tid = threadIdx.x, warp = tid >> 5, lane = tid & 31;
    int row = blockIdx.x * 32 + warp;
    int b = row >> 7, rit = row & 127;
    int lbl = __ldg(&g_lbl[row]);

    // ---- P = <e_row, C[lbl]> - diag ----
    const __nv_bfloat162* er = (const __nv_bfloat162*)(g_en + (size_t)row * DIMK);
    const float2* Cr = (const float2*)(g_C + (size_t)lbl * DIMK);
    float P = 0.f;
    #pragma unroll
    for (int i = 0; i < 4; i++) {
        int idx = lane + 32 * i;
        __nv_bfloat162 v = er[idx];
        float2 c = __ldg(&Cr[idx]);
        P = fmaf(__bfloat162float(v.x), c.x, P);
        P = fmaf(__bfloat162float(v.y), c.y, P);
    }

    // ---- S: columns of tiles (r2, b), r2 < b (coalesced over lanes) ----
    float S = 0.f;
    for (int r2 = lane; r2 < b; r2 += 32)
        S += g_colS[rit][b][r2];

    // ---- S: row segments with r == b ----
    int u0, u1;
    if (b < 32) { u0 = 65 * b; u1 = u0 + (64 - b) - 1; }
    else { int p = 63 - b; u0 = 65 * p + (64 - p); u1 = 65 * (p + 1) - 1; }
    int jlo = (int)(((long long)u0 * ncta) / NJOBS) - 2; if (jlo < 0) jlo = 0;
    int jhi = (int)(((long long)u1 * ncta) / NJOBS) + 2; if (jhi > ncta - 1) jhi = ncta - 1;
    int npairs = (jhi - jlo + 1) * MAXSEG;
    for (int i = lane; i < npairs; i += 32) {
        int qq = jlo + i / MAXSEG, sg = i - (i / MAXSEG) * MAXSEG;
        if (g_seg_r[qq][sg] == b) S += g_S2[qq][sg][rit];
    }

    #pragma unroll
    for (int o = 16; o; o >>= 1) {
        S += __shfl_xor_sync(0xffffffffu, S, o);
        P += __shfl_xor_sync(0xffffffffu, P, o);
    }
    float acc = 0.f;
    if (lane == 0) {
        P -= g_diag[row];  // exclude self from positives
        int cnt = g_hist[lbl] - 1;
        acc = (cnt > 0) ? (TEMP_INV + __logf(S) - (P * TEMP_INV) / (float)cnt) : 0.f;
    }
    __shared__ float ws[32];
    if (lane == 0) ws[warp] = acc;
    __syncthreads();
    if (tid < 32) {
        float v = ws[tid];
        #pragma unroll
        for (int o = 16; o; o >>= 1) v += __shfl_xor_sync(0xffffffffu, v, o);
        if (tid == 0) g_pb[blockIdx.x] = v;
    }
}

// ============================================================================
// Kernel 5: combine 256 block partials -> scalar (deterministic, fixed order)
// ============================================================================
__global__ void combine_kernel(float* __restrict__ out) {
    int tid = threadIdx.x;  // 256
    float v = g_pb[tid];
    #pragma unroll
    for (int o = 16; o; o >>= 1) v += __shfl_xor_sync(0xffffffffu, v, o);
    __shared__ float ws[8];
    if ((tid & 31) == 0) ws[tid >> 5] = v;
    __syncthreads();
    if (tid == 0) {
        float tot = ws[0] + ws[1] + ws[2] + ws[3] + ws[4] + ws[5] + ws[6] + ws[7];
        out[0] = tot / (float)NROWS;
    }
}

// ============================================================================
// Launch
// ============================================================================
extern "C" void kernel_launch(void* const* d_in, const int* in_sizes, int n_in,
                              void* d_out, int out_size) {
    const float* emb;
    const void* lab;
    if (in_sizes[0] == NROWS * DIMK) {
        emb = (const float*)d_in[0];
        lab = d_in[1];
    } else {
        emb = (const float*)d_in[1];
        lab = d_in[0];
    }

    int dev = 0;
    cudaGetDevice(&dev);
    int ncta = 0;
    cudaDeviceGetAttribute(&ncta, cudaDevAttrMultiProcessorCount, dev);
    if (ncta < 100 || ncta > MAXCTA) ncta = 128;

    cudaFuncSetAttribute(gemm_kernel, cudaFuncAttributeMaxDynamicSharedMemorySize, SMEM_TOTAL);

    init_kernel<<<65, 1024>>>((const int*)lab);
    prep_kernel<<<NROWS / 32, 1024>>>(emb, lab);
    gemm_kernel<<<ncta, 512, SMEM_TOTAL>>>(ncta);
    finalize_kernel<<<256, 1024>>>(ncta);
    combine_kernel<<<1, 256>>>((float*)d_out);
}

// round 13
// speedup vs baseline: 1.1048x; 1.0241x over previous
#include <cuda_runtime.h>
#include <cuda_bf16.h>
#include <stdint.h>

// ============================================================================
// Problem constants
// ============================================================================
#define NROWS 8192
#define DIMK  256
#define NLBL  1024
#define NRT   64                       // 128-row tiles
#define NJOBS 2080                     // upper-triangular tiles: 64*65/2
#define MAXSEG 8
#define MAXCTA 256
#define TEMP_INV 14.285714285714286f   // 1/0.07
// exp((d-1)/T) = 2^(d*K - K), K = (1/T)*log2(e)
#define K_EX2 20.609929191666664f

// ============================================================================
// Device scratch (no allocation allowed)
// ============================================================================
__device__ __align__(128) __nv_bfloat16 g_en[NROWS * DIMK];  // normalized rows, bf16
__device__ int   g_lbl[NROWS];
__device__ int   g_hist[NLBL];
__device__ int   g_is64;
__device__ float g_dsum[NLBL];                  // per-class sum of self-dots
__device__ __align__(128) float g_C[NLBL * DIMK];  // class-sum vectors (fp32)
__device__ float g_colS[128][NRT][NRT];         // col exp-sums: [rit][ctile][rtile]
__device__ float g_S2[MAXCTA][MAXSEG][128];     // per-(CTA, segment) row exp-sum partials
__device__ int   g_seg_r[MAXCTA][MAXSEG];       // rtile id of each segment
__device__ float g_pb[256];                     // per-block partial losses

// ============================================================================
// PTX helpers (baseline sm_80+ only — target is compute_103 WITHOUT 'a')
// ============================================================================
__device__ __forceinline__ uint32_t smem_u32(const void* p) {
    uint32_t a;
    asm("{ .reg .u64 t; cvta.to.shared.u64 t, %1; cvt.u32.u64 %0, t; }" : "=r"(a) : "l"(p));
    return a;
}

__device__ __forceinline__ void cp16(uint32_t dst, const void* src) {
    asm volatile("cp.async.cg.shared.global [%0], [%1], 16;" :: "r"(dst), "l"(src));
}
#define CP_COMMIT() asm volatile("cp.async.commit_group;" ::: "memory")
#define CP_WAIT0()  asm volatile("cp.async.wait_group 0;" ::: "memory")

__device__ __forceinline__ void ldsm4(uint32_t* r, uint32_t addr) {
    asm volatile("ldmatrix.sync.aligned.m8n8.x4.shared.b16 {%0,%1,%2,%3}, [%4];"
        : "=r"(r[0]), "=r"(r[1]), "=r"(r[2]), "=r"(r[3]) : "r"(addr));
}

__device__ __forceinline__ void mma16816(float* d, const uint32_t* a, const uint32_t* b) {
    asm volatile(
        "mma.sync.aligned.m16n8k16.row.col.f32.bf16.bf16.f32 "
        "{%0,%1,%2,%3}, {%4,%5,%6,%7}, {%8,%9}, {%0,%1,%2,%3};"
        : "+f"(d[0]), "+f"(d[1]), "+f"(d[2]), "+f"(d[3])
        : "r"(a[0]), "r"(a[1]), "r"(a[2]), "r"(a[3]), "r"(b[0]), "r"(b[1]));
}

__device__ __forceinline__ float ex2f(float x) {
    float e;
    asm("ex2.approx.f32 %0, %1;" : "=f"(e) : "f"(x));
    return e;
}

// ============================================================================
// SMEM layout (padded K-major tiles: 128 rows x 264 bf16 -> 528 B row stride)
// ============================================================================
#define ROWB   528
#define TILEB  (128 * ROWB)                 // 67584
#define SOFF_A   0
#define SOFF_B0  TILEB
#define SOFF_ROW (3 * TILEB)                // sS[4][128] (2 KB)
#define SOFF_COL (3 * TILEB + 2048)         // sCS[2][4][128] (4 KB)
#define SMEM_TOTAL (3 * TILEB + 2048 + 4096)  // 208896

// Fill one 128-row x 256-col bf16 tile via cp.async. 512 threads, 4096 chunks.
__device__ __forceinline__ void load_tile(uint32_t dst_base, int grow_base, int tid) {
    #pragma unroll
    for (int i = 0; i < 8; i++) {
        int c = tid + i * 512;     // 0..4095
        int r = c >> 5;            // row
        int q = c & 31;            // 16B chunk
        cp16(dst_base + r * ROWB + q * 16,
             (const void*)(g_en + (size_t)(grow_base + r) * DIMK + q * 8));
    }
}

// ============================================================================
// Kernel 1: block 0: zero hist/dsum/seg_r + detect labels dtype;
// blocks 1..64: zero g_C
// ============================================================================
__global__ void init_kernel(const int* lab32) {
    int tid = threadIdx.x;  // 1024
    if (blockIdx.x == 0) {
        if (tid < NLBL) {
            g_hist[tid] = 0;
            g_dsum[tid] = 0.f;
        }
        if (tid < MAXCTA * MAXSEG) ((int*)g_seg_r)[tid] = -1;
        if (tid + 1024 < MAXCTA * MAXSEG) ((int*)g_seg_r)[tid + 1024] = -1;
        __shared__ int any;
        if (tid == 0) any = 0;
        __syncthreads();
        for (int i = tid; i < 4096; i += 1024)
            if (lab32[2 * i + 1] != 0) any = 1;  // benign race
        __syncthreads();
        if (tid == 0) g_is64 = (any == 0) ? 1 : 0;
    } else {
        ((float4*)g_C)[(blockIdx.x - 1) * 1024 + tid] = make_float4(0.f, 0.f, 0.f, 0.f);
    }
}

// ============================================================================
// Kernel 2: normalize rows -> bf16 (warp per row), labels, histogram,
// per-class self-dot sum, class-sum accumulation (fp32 atomics)
// ============================================================================
__global__ void prep_kernel(const float* __restrict__ emb, const void* __restrict__ labels) {
    int warp = threadIdx.x >> 5, lane = threadIdx.x & 31;
    int row = blockIdx.x * 8 + warp;
    const float4* src = (const float4*)(emb + (size_t)row * DIMK);
    float4 v0 = __ldg(src + lane);
    float4 v1 = __ldg(src + lane + 32);
    float ss = v0.x * v0.x + v0.y * v0.y + v0.z * v0.z + v0.w * v0.w
             + v1.x * v1.x + v1.y * v1.y + v1.z * v1.z + v1.w * v1.w;
    #pragma unroll
    for (int o = 16; o; o >>= 1) ss += __shfl_xor_sync(0xffffffffu, ss, o);
    float inv = 1.0f / fmaxf(sqrtf(ss), 1e-12f);
    __nv_bfloat16 b[8];
    b[0] = __float2bfloat16(v0.x * inv); b[1] = __float2bfloat16(v0.y * inv);
    b[2] = __float2bfloat16(v0.z * inv); b[3] = __float2bfloat16(v0.w * inv);
    b[4] = __float2bfloat16(v1.x * inv); b[5] = __float2bfloat16(v1.y * inv);
    b[6] = __float2bfloat16(v1.z * inv); b[7] = __float2bfloat16(v1.w * inv);
    __nv_bfloat162* d2 = (__nv_bfloat162*)(g_en + (size_t)row * DIMK);
    d2[2 * lane + 0]  = __nv_bfloat162(b[0], b[1]);
    d2[2 * lane + 1]  = __nv_bfloat162(b[2], b[3]);
    d2[64 + 2 * lane] = __nv_bfloat162(b[4], b[5]);
    d2[65 + 2 * lane] = __nv_bfloat162(b[6], b[7]);
    float f[8], dd = 0.f;
    #pragma unroll
    for (int i = 0; i < 8; i++) {
        f[i] = __bfloat162float(b[i]);
        dd = fmaf(f[i], f[i], dd);
    }
    #pragma unroll
    for (int o = 16; o; o >>= 1) dd += __shfl_xor_sync(0xffffffffu, dd, o);
    int l;
    if (lane == 0) {
        l = g_is64 ? (int)((const long long*)labels)[row] : ((const int*)labels)[row];
        g_lbl[row] = l;
        atomicAdd(&g_hist[l], 1);
        atomicAdd(&g_dsum[l], dd);
    }
    l = __shfl_sync(0xffffffffu, l, 0);
    float* Cr = g_C + (size_t)l * DIMK;
    #pragma unroll
    for (int i = 0; i < 4; i++) atomicAdd(&Cr[4 * lane + i], f[i]);
    #pragma unroll
    for (int i = 0; i < 4; i++) atomicAdd(&Cr[128 + 4 * lane + i], f[4 + i]);
}

// ============================================================================
// Kernel 3: persistent symmetric fused GEMM (pair-folded triangular jobs).
// 512 threads = 16 warps (4M x 4N, 32x32 warp tiles). One exp feeds both
// row exp-sums (block r) and column exp-sums (block c). NO label work here.
// ============================================================================
typedef float Acc[2][4][4];  // [mf][j][r]

// reduce column partials across the 8 row-positions (lanes xor 4,8,16) + store
__device__ __forceinline__ void col_flush(
    char* smem, float* cS, int par, int warpM, int warpN, int lid)
{
    float* sCS = (float*)(smem + SOFF_COL) + par * 512;
    #pragma unroll
    for (int cj = 0; cj < 8; cj++) {
        float s = cS[cj];
        s += __shfl_xor_sync(0xffffffffu, s, 4);
        s += __shfl_xor_sync(0xffffffffu, s, 8);
        s += __shfl_xor_sync(0xffffffffu, s, 16);
        if (lid < 4) {
            int col = warpN * 32 + (cj >> 1) * 8 + 2 * lid + (cj & 1);
            sCS[warpM * 128 + col] = s;
        }
        cS[cj] = 0.f;
    }
}

template <bool HAS_PREV>
__device__ __forceinline__ void do_tile(
    int jc, int c_cur, int r, int segEnd, char* smem, uint32_t sb,
    int tid, int lid, int warpM, int warpN,
    uint32_t aAddr, uint32_t bOff,
    Acc& cur, Acc& prev, float* Sa, float* cS,
    int& pend_c, bool prev_offd)
{
    CP_WAIT0();
    __syncthreads();

    // prefetch next B tile within this segment
    if (jc + 1 < segEnd) {
        load_tile(sb + SOFF_B0 + ((jc + 1) & 1) * TILEB, (c_cur + 1) << 7, tid);
        CP_COMMIT();
    }
    // store previously-flushed column sums (parity of tile jc-2, safe post-sync)
    if (HAS_PREV && pend_c >= 0 && tid < 128) {
        float* sCS = (float*)(smem + SOFF_COL) + (jc & 1) * 512;  // (jc-2)&1 == jc&1
        g_colS[tid][pend_c][r] = sCS[tid] + sCS[128 + tid] + sCS[256 + tid] + sCS[384 + tid];
    }

    #pragma unroll
    for (int mf = 0; mf < 2; mf++)
        #pragma unroll
        for (int j = 0; j < 4; j++)
            #pragma unroll
            for (int rr = 0; rr < 4; rr++) cur[mf][j][rr] = 0.f;

    uint32_t bAddr = sb + SOFF_B0 + (jc & 1) * TILEB + bOff;

    #pragma unroll
    for (int ks = 0; ks < 16; ks++) {
        uint32_t a[2][4], b[2][4];
        ldsm4(a[0], aAddr + ks * 32);
        ldsm4(a[1], aAddr + 16 * ROWB + ks * 32);
        ldsm4(b[0], bAddr + ks * 32);
        ldsm4(b[1], bAddr + 16 * ROWB + ks * 32);
        #pragma unroll
        for (int mf = 0; mf < 2; mf++)
            #pragma unroll
            for (int jj = 0; jj < 2; jj++) {
                mma16816(cur[mf][2 * jj + 0], a[mf], &b[jj][0]);
                mma16816(cur[mf][2 * jj + 1], a[mf], &b[jj][2]);
            }
        if (HAS_PREV) {
            // interleaved epilogue: 2 values of previous tile's acc per ks step
            #pragma unroll
            for (int u = 0; u < 2; u++) {
                const int v = 2 * ks + u;
                const int mf = v >> 4, j = (v >> 2) & 3, rr = v & 3;
                const int hi = rr >> 1, lo = rr & 1;
                float e = ex2f(fmaf(prev[mf][j][rr], K_EX2, -K_EX2));
                Sa[mf * 2 + hi] += e;
                cS[j * 2 + lo] += e;
            }
        }
    }

    if (HAS_PREV) {
        if (prev_offd) {
            col_flush(smem, cS, (jc - 1) & 1, warpM, warpN, lid);
            pend_c = c_cur - 1;
        } else {
            // previous tile was the diagonal: its column sums are already
            // counted as rows — discard
            #pragma unroll
            for (int i = 0; i < 8; i++) cS[i] = 0.f;
            pend_c = -1;
        }
    }
}

__device__ __forceinline__ void drain_acc(Acc& acc, float* Sa, float* cS) {
    #pragma unroll
    for (int v = 0; v < 32; v++) {
        const int mf = v >> 4, j = (v >> 2) & 3, rr = v & 3;
        const int hi = rr >> 1, lo = rr & 1;
        float e = ex2f(fmaf(acc[mf][j][rr], K_EX2, -K_EX2));
        Sa[mf * 2 + hi] += e;
        cS[j * 2 + lo] += e;
    }
}

__global__ void __launch_bounds__(512, 1) gemm_kernel(int ncta) {
    extern __shared__ char smem[];
    uint32_t sb = smem_u32(smem);
    float (*sS)[128] = (float(*)[128])(smem + SOFF_ROW);
    int tid = threadIdx.x, wid = tid >> 5, lid = tid & 31;
    int warpM = wid & 3, warpN = wid >> 2;  // 4 x 4 warp grid, 32x32 warp tiles
    int bid = blockIdx.x;
    int start = (bid * NJOBS) / ncta;
    int end = ((bid + 1) * NJOBS) / ncta;

    // row-in-tile covered by each of this lane's 4 acc row-groups
    int rit[4];
    #pragma unroll
    for (int idx = 0; idx < 4; idx++)
        rit[idx] = warpM * 32 + (idx >> 1) * 16 + (idx & 1) * 8 + (lid >> 2);

    // ldmatrix per-lane base addresses
    uint32_t aAddr = sb + SOFF_A
        + (uint32_t)(warpM * 32 + (lid & 7) + ((lid >> 3) & 1) * 8) * ROWB
        + ((lid >> 4) & 1) * 16;
    uint32_t bOff =
        (uint32_t)(warpN * 32 + (lid & 7) + ((lid >> 4) & 1) * 8) * ROWB
        + ((lid >> 3) & 1) * 16;

    Acc acc0, acc1;
    float Sa[4], cS[8];
    #pragma unroll
    for (int i = 0; i < 8; i++) cS[i] = 0.f;

    int job = start, seg = 0, pend_c = -1;

    while (job < end) {
        // decode pair-folded run containing job:
        // pair p = row p (head, 64-p jobs) then row 63-p (tail, p+1 jobs)
        int p = job / 65, q = job - 65 * p, h = 64 - p;
        int r, run_start, run_end;
        if (q < h) { r = p;      run_start = 65 * p;     run_end = run_start + h; }
        else       { r = 63 - p; run_start = 65 * p + h; run_end = 65 * (p + 1);  }
        int segEnd = min(end, run_end);
        int row_base = r << 7;
        int c0 = r + (job - run_start);
        #pragma unroll
        for (int idx = 0; idx < 4; idx++) Sa[idx] = 0.f;

        // segment prologue: A tile + first B tile as one cp.async group
        load_tile(sb + SOFF_A, row_base, tid);
        load_tile(sb + SOFF_B0 + (job & 1) * TILEB, c0 << 7, tid);
        CP_COMMIT();

        int n = segEnd - job;
        do_tile<false>(job, c0, r, segEnd, smem, sb, tid, lid, warpM, warpN,
                       aAddr, bOff, acc0, acc1, Sa, cS, pend_c, false);
        int k = 1;
        while (k + 2 <= n) {
            do_tile<true>(job + k, c0 + k, r, segEnd, smem, sb, tid, lid, warpM, warpN,
                          aAddr, bOff, acc1, acc0, Sa, cS, pend_c, (c0 + k - 1) != r);
            do_tile<true>(job + k + 1, c0 + k + 1, r, segEnd, smem, sb, tid, lid, warpM, warpN,
                          aAddr, bOff, acc0, acc1, Sa, cS, pend_c, true);
            k += 2;
        }
        int cL = c0 + n - 1;            // column of last tile
        bool offd_last = (cL != r);
        if (k < n) {
            do_tile<true>(job + k, c0 + k, r, segEnd, smem, sb, tid, lid, warpM, warpN,
                          aAddr, bOff, acc1, acc0, Sa, cS, pend_c, (c0 + k - 1) != r);
            drain_acc(acc1, Sa, cS);
        } else {
            drain_acc(acc0, Sa, cS);
        }

        // flush last tile's columns (or discard if it was the diagonal)
        int parL = (segEnd - 1) & 1;
        if (offd_last) {
            col_flush(smem, cS, parL, warpM, warpN, lid);
        } else {
            #pragma unroll
            for (int i = 0; i < 8; i++) cS[i] = 0.f;
        }

        // row partials: quad reduce -> smem
        #pragma unroll
        for (int idx = 0; idx < 4; idx++) {
            float s = Sa[idx];
            s += __shfl_xor_sync(0xffffffffu, s, 1);
            s += __shfl_xor_sync(0xffffffffu, s, 2);
            if ((lid & 3) == 0) sS[warpN][rit[idx]] = s;
        }
        __syncthreads();
        if (tid < 128) {
            if (pend_c >= 0) {   // second-to-last tile's columns
                float* sCS = (float*)(smem + SOFF_COL) + ((segEnd - 2) & 1) * 512;
                g_colS[tid][pend_c][r] = sCS[tid] + sCS[128 + tid] + sCS[256 + tid] + sCS[384 + tid];
            }
            if (offd_last) {     // last tile's columns
                float* sCS = (float*)(smem + SOFF_COL) + parL * 512;
                g_colS[tid][cL][r] = sCS[tid] + sCS[128 + tid] + sCS[256 + tid] + sCS[384 + tid];
            }
            g_S2[bid][seg][tid] = sS[0][tid] + sS[1][tid] + sS[2][tid] + sS[3][tid];
        }
        if (tid == 0) g_seg_r[bid][seg] = r;
        __syncthreads();  // protects smem buffers before next segment
        pend_c = -1;
        job = segEnd;
        seg++;
    }
}

// ============================================================================
// Kernel 4: per-row loss, warp per row. 256 blocks x 1024 threads.
// S: coalesced column gather + lane-parallel segment scan.
// Positive term handled per-CLASS: warps with row < NLBL subtract
// TEMP_INV*(|C_c|^2 - dsum_c)/(cnt_c-1) for class c == row.
// ============================================================================
__global__ void finalize_kernel(int ncta) {
    int tid = threadIdx.x, warp = tid >> 5, lane = tid & 31;
    int row = blockIdx.x * 32 + warp;
    int b = row >> 7, rit = row & 127;
    int lbl = __ldg(&g_lbl[row]);

    // ---- S: columns of tiles (r2, b), r2 < b (coalesced over lanes) ----
    float S = 0.f;
    for (int r2 = lane; r2 < b; r2 += 32)
        S += g_colS[rit][b][r2];

    // ---- S: row segments with r == b ----
    int u0, u1;
    if (b < 32) { u0 = 65 * b; u1 = u0 + (64 - b) - 1; }
    else { int p = 63 - b; u0 = 65 * p + (64 - p); u1 = 65 * (p + 1) - 1; }
    int jlo = (int)(((long long)u0 * ncta) / NJOBS) - 2; if (jlo < 0) jlo = 0;
    int jhi = (int)(((long long)u1 * ncta) / NJOBS) + 2; if (jhi > ncta - 1) jhi = ncta - 1;
    int npairs = (jhi - jlo + 1) * MAXSEG;
    for (int i = lane; i < npairs; i += 32) {
        int qq = jlo + i / MAXSEG, sg = i - (i / MAXSEG) * MAXSEG;
        if (g_seg_r[qq][sg] == b) S += g_S2[qq][sg][rit];
    }

    #pragma unroll
    for (int o = 16; o; o >>= 1) S += __shfl_xor_sync(0xffffffffu, S, o);

    float acc = 0.f;
    if (lane == 0) {
        int cnt = g_hist[lbl];
        acc = (cnt > 1) ? (TEMP_INV + __logf(S)) : 0.f;
    }

    // ---- class term: warps with row < NLBL handle class c = row ----
    if (row < NLBL) {
        int cntc = __ldg(&g_hist[row]);
        if (cntc > 1) {
            const float4* Cc = (const float4*)(g_C + (size_t)row * DIMK);
            float nn = 0.f;
            #pragma unroll
            for (int i = 0; i < 2; i++) {
                float4 v = __ldg(&Cc[lane + 32 * i]);
                nn += v.x * v.x + v.y * v.y + v.z * v.z + v.w * v.w;
            }
            #pragma unroll
            for (int o = 16; o; o >>= 1) nn += __shfl_xor_sync(0xffffffffu, nn, o);
            if (lane == 0)
                acc -= TEMP_INV * (nn - g_dsum[row]) / (float)(cntc - 1);
        }
    }

    __shared__ float ws[32];
    if (lane == 0) ws[warp] = acc;
    __syncthreads();
    if (tid < 32) {
        float v = ws[tid];
        #pragma unroll
        for (int o = 16; o; o >>= 1) v += __shfl_xor_sync(0xffffffffu, v, o);
        if (tid == 0) g_pb[blockIdx.x] = v;
    }
}

// ============================================================================
// Kernel 5: combine 256 block partials -> scalar (deterministic, fixed order)
// ============================================================================
__global__ void combine_kernel(float* __restrict__ out) {
    int tid = threadIdx.x;  // 256
    float v = g_pb[tid];
    #pragma unroll
    for (int o = 16; o; o >>= 1) v += __shfl_xor_sync(0xffffffffu, v, o);
    __shared__ float ws[8];
    if ((tid & 31) == 0) ws[tid >> 5] = v;
    __syncthreads();
    if (tid == 0) {
        float tot = ws[0] + ws[1] + ws[2] + ws[3] + ws[4] + ws[5] + ws[6] + ws[7];
        out[0] = tot / (float)NROWS;
    }
}

// ============================================================================
// Launch
// ============================================================================
extern "C" void kernel_launch(void* const* d_in, const int* in_sizes, int n_in,
                              void* d_out, int out_size) {
    const float* emb;
    const void* lab;
    if (in_sizes[0] == NROWS * DIMK) {
        emb = (const float*)d_in[0];
        lab = d_in[1];
    } else {
        emb = (const float*)d_in[1];
        lab = d_in[0];
    }

    int dev = 0;
    cudaGetDevice(&dev);
    int ncta = 0;
    cudaDeviceGetAttribute(&ncta, cudaDevAttrMultiProcessorCount, dev);
    if (ncta < 100 || ncta > MAXCTA) ncta = 128;

    cudaFuncSetAttribute(gemm_kernel, cudaFuncAttributeMaxDynamicSharedMemorySize, SMEM_TOTAL);

    init_kernel<<<65, 1024>>>((const int*)lab);
    prep_kernel<<<NROWS / 8, 256>>>(emb, lab);
    gemm_kernel<<<ncta, 512, SMEM_TOTAL>>>(ncta);
    finalize_kernel<<<256, 1024>>>(ncta);
    combine_kernel<<<1, 256>>>((float*)d_out);
}